// round 13
// baseline (speedup 1.0000x reference)
#include <cuda_runtime.h>

// UpsampleNearest4D: x (2,8,8,16,64,64) f32, scale=2 on axes 2..5
// -> out (2,8,16,32,128,128) f32.
//
// Input-major (Round-1 pattern: best measured DRAM%), with DOUBLED per-thread
// store batch to raise DRAM write-queue occupancy:
//   one thread: 2 independent input float2 loads (y and y+32), then
//   16 independent STG.128 across 8 replication streams x 2 y-slices.
//   Per warp, every store is a fully-coalesced 512 B transaction
//   (32 lanes x 16 B, consecutive), identical to the Round-1 baseline.
//
// Input  strides (floats): x:1, y:64, z:4096, t:65536, bc:524288  (bc=b*8+c)
// Output strides (floats): x:1, y:128, z:16384, t:524288, bc:8388608

#define THREADS 256u
#define N_THREADS_TOTAL 2097152u   // input float2s / 2 (y-pair) = 2^21

__global__ void __launch_bounds__(256)
upsample4d_x2_mlp2(const float* __restrict__ in, float* __restrict__ out) {
    unsigned i = blockIdx.x * THREADS + threadIdx.x;

    // Decompose (power-of-2 dims -> shifts/masks); y covers [0,32), second
    // element of the pair is at y+32.
    unsigned x2 = i & 31u;            // 32 float2 per input X-row
    unsigned y  = (i >> 5)  & 31u;    // Y base: 32 (pair partner at +32)
    unsigned z  = (i >> 10) & 15u;    // Z: 16
    unsigned t  = (i >> 14) & 7u;     // T: 8
    unsigned bc = (i >> 17);          // B*C: 16

    unsigned in_off = bc * 524288u + t * 65536u + z * 4096u + y * 64u + x2 * 2u;

    // Two independent loads issued back-to-back (MLP=2)
    float2 v0 = *reinterpret_cast<const float2*>(in + in_off);
    float2 v1 = *reinterpret_cast<const float2*>(in + in_off + 2048u); // y+32

    float4 w0 = make_float4(v0.x, v0.x, v0.y, v0.y);
    float4 w1 = make_float4(v1.x, v1.x, v1.y, v1.y);

    unsigned out_base = bc * 8388608u + t * 1048576u + z * 32768u
                      + y * 256u + x2 * 4u;

    float* o0 = out + out_base;           // rows 2y, 2y+1 region
    float* o1 = o0 + 8192u;               // rows 2(y+32), +1 region (+32*256)

#pragma unroll
    for (unsigned dt = 0; dt < 2; ++dt) {
#pragma unroll
        for (unsigned dz = 0; dz < 2; ++dz) {
#pragma unroll
            for (unsigned dy = 0; dy < 2; ++dy) {
                unsigned off = dt * 524288u + dz * 16384u + dy * 128u;
                *reinterpret_cast<float4*>(o0 + off) = w0;
                *reinterpret_cast<float4*>(o1 + off) = w1;
            }
        }
    }
}

extern "C" void kernel_launch(void* const* d_in, const int* in_sizes, int n_in,
                              void* d_out, int out_size) {
    const float* x = (const float*)d_in[0];
    float* out = (float*)d_out;
    // scale_factor (d_in[1]) fixed at 2 for this problem's shapes; hardcoded.
    unsigned blocks = N_THREADS_TOTAL / THREADS;   // 8192
    upsample4d_x2_mlp2<<<blocks, THREADS>>>(x, out);
}